// round 6
// baseline (speedup 1.0000x reference)
#include <cuda_runtime.h>
#include <cstdint>

// Problem constants (fixed by the reference)
#define NB  32
#define MP  30
#define KJ  17
#define KHW (17 * 256 * 256)   // 1114112
#define MK  (MP * KJ)          // 510  joints per image
#define NI4 (MK * 2 / 4)       // 255  int4 words of joints per image
#define MU_INVALID 1e18f       // sentinel: exp(-(d^2)) underflows to 0

// One warp per batch image. Coalesced joints load; predicated gather;
// SoA smem redistribution (conflict-free stride-17); sentinel-mu push;
// pull butterfly hoisted to overlap the push loop; dual-lane output store.
__global__ __launch_bounds__(32, 1)
void ae_loss_kernel(const float* __restrict__ tags,
                    const int*   __restrict__ joints,
                    float*       __restrict__ out) {
    const int n = blockIdx.x;
    const float* tg = tags + (size_t)n * KHW;
    const int4*  j4 = reinterpret_cast<const int4*>(joints + (size_t)n * MK * 2);

    const int lane = threadIdx.x;

    __shared__ float s_v[MK];   // visibility per joint
    __shared__ float s_t[MK];   // masked tag per joint

    // ---- Phase A: coalesced joints load, predicated gather, scatter to smem ----
    #pragma unroll
    for (int w = 0; w < 8; w++) {
        int m = lane + 32 * w;                  // int4 index = joints 2m, 2m+1
        if (m < NI4) {
            int4 q = __ldg(&j4[m]);
            float v0 = (q.y > 0) ? 1.0f : 0.0f;
            float v1 = (q.w > 0) ? 1.0f : 0.0f;
            float t0 = 0.0f, t1 = 0.0f;
            if (q.y > 0) t0 = __ldg(tg + q.x);  // skip invisible joints
            if (q.w > 0) t1 = __ldg(tg + q.z);
            s_v[2 * m]     = v0;
            s_v[2 * m + 1] = v1;
            s_t[2 * m]     = t0;
            s_t[2 * m + 1] = t1;
        }
    }
    __syncwarp();

    // ---- Phase B: per-person stats (lane p owns person p; stride 17 -> no bank conflicts) ----
    float mu = MU_INVALID, pvf = 0.0f, pull = 0.0f;
    if (lane < MP) {
        float cnt = 0.0f, s1 = 0.0f, s2 = 0.0f;
        #pragma unroll
        for (int k = 0; k < KJ; k++) {
            float v = s_v[lane * KJ + k];
            float t = s_t[lane * KJ + k];
            cnt += v;
            s1  += t;
            s2  += t * t;   // t already masked; t^2 == v*t^2 since v in {0,1}
        }
        if (cnt > 0.0f) {
            float rcs = __fdividef(1.0f, cnt);
            mu   = s1 * rcs;
            pvf  = 1.0f;
            pull = fmaxf(s2 - cnt * mu * mu, 0.0f) * rcs;
        }
    }

    // n (valid-person count) via ballot.
    unsigned bal = __ballot_sync(0xffffffffu, pvf > 0.0f);
    float nn = (float)__popc(bal);

    // ---- Pull butterfly (hoisted: its dependent SHFL chain overlaps the push loop) ----
    #pragma unroll
    for (int o = 16; o > 0; o >>= 1)
        pull += __shfl_xor_sync(0xffffffffu, pull, o);

    // ---- Phase C: push via rotation, symmetry-halved, sentinel-masked ----
    // sum over ordered off-diagonal pairs = 2*sum(off=1..14) + sum(off=15).
    float psum2 = 0.0f, psum1 = 0.0f;
    #pragma unroll
    for (int off = 1; off <= 15; off++) {
        int src = lane + off;
        if (src >= MP) src -= MP;
        float muj = __shfl_sync(0xffffffffu, mu, src);
        float d = mu - muj;
        float term = __expf(-d * d);
        if (off < 15) psum2 += term; else psum1 = term;
    }
    float psum = pvf * fmaf(2.0f, psum2, psum1);

    // ---- Push butterfly ----
    #pragma unroll
    for (int o = 16; o > 0; o >>= 1)
        psum += __shfl_xor_sync(0xffffffffu, psum, o);

    // Butterfly leaves full sums in ALL lanes: lane 0 and lane 1 store in parallel.
    if (lane == 0) {
        float denom = fmaxf((nn - 1.0f) * nn, 1.0f);
        out[n] = psum * __fdividef(0.5f, denom);                 // pushes [0..31]
    } else if (lane == 1) {
        out[NB + n] = pull * __fdividef(1.0f, fmaxf(nn, 1.0f));  // pulls [32..63]
    }
}

extern "C" void kernel_launch(void* const* d_in, const int* in_sizes, int n_in,
                              void* d_out, int out_size) {
    const float* tags   = (const float*)d_in[0];  // [N, KHW, 1] float32
    const int*   joints = (const int*)d_in[1];    // [N, M, K, 2] int32
    float* out = (float*)d_out;                   // [2*N] = pushes ++ pulls
    ae_loss_kernel<<<NB, 32>>>(tags, joints, out);
}